// round 4
// baseline (speedup 1.0000x reference)
#include <cuda_runtime.h>

// convection_vectors: (N_NODES, 3) float32      -> d_in[0]
// mesh_elements:      (E, 4)       int32        -> d_in[1]
// inv_matrices:       (E, 4, 4)    float32      -> d_in[2]
// out:                (E, 4, 3)    float32      -> d_out
//
// out[e,i,c] = sum_j inv[e,i,j] * conv[mesh[e,j], c]

#define MAX_NODES 400000

// Padded gather table: (N, 4) so each vertex is one aligned 16B load. 6.4 MB -> L2-resident.
__device__ float4 g_conv4[MAX_NODES];

// Thread per node (R2 version — fastest pad so far).
__global__ void __launch_bounds__(256)
pad_conv_kernel(const float* __restrict__ conv, int n)
{
    int i = blockIdx.x * blockDim.x + threadIdx.x;
    if (i >= n) return;
    long b = (long)i * 3;
    g_conv4[i] = make_float4(conv[b], conv[b + 1], conv[b + 2], 0.0f);
}

// Layout: 2 elements per warp, 16 lanes per element.
//  - each gather LDG touches only 2 distinct 128B lines (replay cost 1+2.07
//    instead of 1+7*2.07 with 8 lines/instr)
//  - inv: 8 distinct rows of 2 consecutive matrices = one 128B line / instr
//  - elems: 2 consecutive int4 = 1 line (broadcast within halves)
//  - store: lane s<12 writes out[e*12+s]; warp covers 96B contiguous, 1 STG
__global__ void __launch_bounds__(256)
fem_pair_kernel(const int4*   __restrict__ elems,
                const float4* __restrict__ inv,
                float*        __restrict__ out,
                int E)
{
    int t    = blockIdx.x * blockDim.x + threadIdx.x;
    int warp = t >> 5;
    int lane = t & 31;
    int h    = lane >> 4;     // which of the 2 elements
    int s    = lane & 15;     // slot within element: s<12 -> (row, comp)

    int e = warp * 2 + h;
    bool valid = (e < E);
    int ec = valid ? e : (E - 1);   // clamp for safe loads

    // element vertex indices (all 16 lanes of the element read the same int4)
    int4 idx = __ldcs(&elems[ec]);

    // this lane's matrix row: s = row*3 + comp
    int row  = s / 3;          // 0..3 (s<12); s>=12 harmless
    int comp = s - 3 * row;    // 0..2
    int row4 = (row < 4) ? row : 3;

    float4 m = __ldcs(&inv[(long)ec * 4 + row4]);

    // gathers: 4 instrs, each touching only 2 distinct lines (one per element)
    float4 v0 = g_conv4[idx.x];
    float4 v1 = g_conv4[idx.y];
    float4 v2 = g_conv4[idx.z];
    float4 v3 = g_conv4[idx.w];

    // select component `comp` of each vertex (2 SELs per vertex)
    float a0 = (comp == 0) ? v0.x : ((comp == 1) ? v0.y : v0.z);
    float a1 = (comp == 0) ? v1.x : ((comp == 1) ? v1.y : v1.z);
    float a2 = (comp == 0) ? v2.x : ((comp == 1) ? v2.y : v2.z);
    float a3 = (comp == 0) ? v3.x : ((comp == 1) ? v3.y : v3.z);

    float r = fmaf(m.x, a0, fmaf(m.y, a1, fmaf(m.z, a2, m.w * a3)));

    if (valid && s < 12)
        __stcs(out + (long)e * 12 + s, r);
}

extern "C" void kernel_launch(void* const* d_in, const int* in_sizes, int n_in,
                              void* d_out, int out_size)
{
    const float* conv  = (const float*)d_in[0];
    const int4*  elems = (const int4*)d_in[1];
    const float4* inv  = (const float4*)d_in[2];
    float* out = (float*)d_out;

    int n_nodes = in_sizes[0] / 3;
    int E = in_sizes[1] / 4;

    int block = 256;
    pad_conv_kernel<<<(n_nodes + block - 1) / block, block>>>(conv, n_nodes);

    // one warp per 2 elements -> 16 threads per element
    long total_threads = (long)((E + 1) / 2) * 32;
    int grid = (int)((total_threads + block - 1) / block);
    fem_pair_kernel<<<grid, block>>>(elems, inv, out, E);
}

// round 5
// speedup vs baseline: 2.1126x; 2.1126x over previous
#include <cuda_runtime.h>

// convection_vectors: (N_NODES, 3) float32      -> d_in[0]
// mesh_elements:      (E, 4)       int32        -> d_in[1]
// inv_matrices:       (E, 4, 4)    float32      -> d_in[2]
// out:                (E, 4, 3)    float32      -> d_out
//
// out[e,i,c] = sum_j inv[e,i,j] * conv[mesh[e,j], c]

#define MAX_NODES 400000

// Padded gather table: (N, 4) so each vertex is one aligned 16B load. 6.4 MB -> L2-resident.
__device__ float4 g_conv4[MAX_NODES];

__global__ void __launch_bounds__(256)
pad_conv_kernel(const float* __restrict__ conv, int n)
{
    int i = blockIdx.x * blockDim.x + threadIdx.x;
    if (i >= n) return;
    long b = (long)i * 3;
    g_conv4[i] = make_float4(conv[b], conv[b + 1], conv[b + 2], 0.0f);
}

// R2 layout (one thread per (element,row) unit, warp-coalesced) + ILP=2:
// each thread processes units t0 = tid and t1 = tid + 2E. All loads of both
// chains are front-issued -> ~12 outstanding lines per thread to hide L2/DRAM
// latency. Plain scalar stores (3 lines per STG instr, measured cheaper than
// shuffle-transpose at current L1 duty).
__global__ void __launch_bounds__(256)
fem_row2_kernel(const int4*   __restrict__ elems,
                const float4* __restrict__ inv,
                float*        __restrict__ out,
                int half_rows)   // 2*E
{
    int t0 = blockIdx.x * blockDim.x + threadIdx.x;
    if (t0 >= half_rows) return;
    int t1 = t0 + half_rows;

    // Front-issued independent load chains.
    int4 iA = __ldcs(&elems[t0 >> 2]);
    int4 iB = __ldcs(&elems[t1 >> 2]);
    float4 mA = __ldcs(&inv[t0]);
    float4 mB = __ldcs(&inv[t1]);

    float4 a0 = g_conv4[iA.x];
    float4 a1 = g_conv4[iA.y];
    float4 a2 = g_conv4[iA.z];
    float4 a3 = g_conv4[iA.w];
    float4 c0 = g_conv4[iB.x];
    float4 c1 = g_conv4[iB.y];
    float4 c2 = g_conv4[iB.z];
    float4 c3 = g_conv4[iB.w];

    float rA0 = fmaf(mA.x, a0.x, fmaf(mA.y, a1.x, fmaf(mA.z, a2.x, mA.w * a3.x)));
    float rA1 = fmaf(mA.x, a0.y, fmaf(mA.y, a1.y, fmaf(mA.z, a2.y, mA.w * a3.y)));
    float rA2 = fmaf(mA.x, a0.z, fmaf(mA.y, a1.z, fmaf(mA.z, a2.z, mA.w * a3.z)));

    float rB0 = fmaf(mB.x, c0.x, fmaf(mB.y, c1.x, fmaf(mB.z, c2.x, mB.w * c3.x)));
    float rB1 = fmaf(mB.x, c0.y, fmaf(mB.y, c1.y, fmaf(mB.z, c2.y, mB.w * c3.y)));
    float rB2 = fmaf(mB.x, c0.z, fmaf(mB.y, c1.z, fmaf(mB.z, c2.z, mB.w * c3.z)));

    float* o0 = out + (long)t0 * 3;
    __stcs(o0 + 0, rA0);
    __stcs(o0 + 1, rA1);
    __stcs(o0 + 2, rA2);
    float* o1 = out + (long)t1 * 3;
    __stcs(o1 + 0, rB0);
    __stcs(o1 + 1, rB1);
    __stcs(o1 + 2, rB2);
}

extern "C" void kernel_launch(void* const* d_in, const int* in_sizes, int n_in,
                              void* d_out, int out_size)
{
    const float* conv  = (const float*)d_in[0];
    const int4*  elems = (const int4*)d_in[1];
    const float4* inv  = (const float4*)d_in[2];
    float* out = (float*)d_out;

    int n_nodes = in_sizes[0] / 3;
    int E = in_sizes[1] / 4;
    int half_rows = 2 * E;

    int block = 256;
    pad_conv_kernel<<<(n_nodes + block - 1) / block, block>>>(conv, n_nodes);
    fem_row2_kernel<<<(half_rows + block - 1) / block, block>>>(elems, inv, out, half_rows);
}

// round 6
// speedup vs baseline: 2.2674x; 1.0733x over previous
#include <cuda_runtime.h>
#include <cstdint>

// convection_vectors: (N_NODES, 3) float32      -> d_in[0]
// mesh_elements:      (E, 4)       int32        -> d_in[1]
// inv_matrices:       (E, 4, 4)    float32      -> d_in[2]
// out:                (E, 4, 3)    float32      -> d_out
//
// out[e,i,c] = sum_j inv[e,i,j] * conv[mesh[e,j], c]

#define MAX_NODES 400000

// Padded gather table: (N, 4) so each vertex is one aligned 16B load. 6.4 MB -> L2-resident.
__device__ float4 g_conv4[MAX_NODES];

__global__ void __launch_bounds__(256)
pad_conv_kernel(const float* __restrict__ conv, int n)
{
    int i = blockIdx.x * blockDim.x + threadIdx.x;
    if (i >= n) return;
    long b = (long)i * 3;
    g_conv4[i] = make_float4(conv[b], conv[b + 1], conv[b + 2], 0.0f);
}

__device__ __forceinline__ uint32_t smem_u32(const void* p)
{
    uint32_t a;
    asm("{ .reg .u64 t; cvta.to.shared.u64 t, %1; cvt.u32.u64 %0, t; }" : "=r"(a) : "l"(p));
    return a;
}

// One thread per (element,row) unit. Stores staged in smem (conflict-free
// stride-3 STS), then one 3KB contiguous tile per block is written with a
// 1D TMA bulk store — removing 6 of 9 store wavefronts per warp from the
// L1 pipe and all per-lane STG issue slots.
__global__ void __launch_bounds__(256)
fem_row_tma_kernel(const int4*   __restrict__ elems,
                   const float4* __restrict__ inv,
                   float*        __restrict__ out,
                   int total_rows)   // 4*E
{
    __shared__ __align__(16) float s_out[256 * 3];   // 3 KB tile

    int block_base = blockIdx.x * blockDim.x;
    int t = block_base + threadIdx.x;
    bool full_block = (block_base + 256 <= total_rows);

    if (t < total_rows) {
        int4 idx = __ldcs(&elems[t >> 2]);
        float4 m = __ldcs(&inv[t]);

        float4 v0 = g_conv4[idx.x];
        float4 v1 = g_conv4[idx.y];
        float4 v2 = g_conv4[idx.z];
        float4 v3 = g_conv4[idx.w];

        float r0 = fmaf(m.x, v0.x, fmaf(m.y, v1.x, fmaf(m.z, v2.x, m.w * v3.x)));
        float r1 = fmaf(m.x, v0.y, fmaf(m.y, v1.y, fmaf(m.z, v2.y, m.w * v3.y)));
        float r2 = fmaf(m.x, v0.z, fmaf(m.y, v1.z, fmaf(m.z, v2.z, m.w * v3.z)));

        if (full_block) {
            // stride-3 word addresses: banks (3L+c) mod 32, gcd(3,32)=1 -> conflict-free
            int w = threadIdx.x * 3;
            s_out[w + 0] = r0;
            s_out[w + 1] = r1;
            s_out[w + 2] = r2;
        } else {
            float* o = out + (long)t * 3;
            __stcs(o + 0, r0);
            __stcs(o + 1, r1);
            __stcs(o + 2, r2);
        }
    }

    if (full_block) {
        // Make generic-proxy STS visible to the async proxy, then sync the tile.
        asm volatile("fence.proxy.async.shared::cta;" ::: "memory");
        __syncthreads();
        if (threadIdx.x == 0) {
            uint32_t saddr = smem_u32(s_out);
            float* gptr = out + (long)block_base * 3;   // 3072B-aligned chunk
            asm volatile(
                "cp.async.bulk.global.shared::cta.bulk_group [%0], [%1], %2;"
                :: "l"(gptr), "r"(saddr), "r"(256 * 3 * 4) : "memory");
            asm volatile("cp.async.bulk.commit_group;" ::: "memory");
            asm volatile("cp.async.bulk.wait_group 0;" ::: "memory");
        }
    }
}

extern "C" void kernel_launch(void* const* d_in, const int* in_sizes, int n_in,
                              void* d_out, int out_size)
{
    const float* conv  = (const float*)d_in[0];
    const int4*  elems = (const int4*)d_in[1];
    const float4* inv  = (const float4*)d_in[2];
    float* out = (float*)d_out;

    int n_nodes = in_sizes[0] / 3;
    int E = in_sizes[1] / 4;
    int total_rows = 4 * E;

    int block = 256;
    pad_conv_kernel<<<(n_nodes + block - 1) / block, block>>>(conv, n_nodes);
    fem_row_tma_kernel<<<(total_rows + block - 1) / block, block>>>(elems, inv, out, total_rows);
}

// round 7
// speedup vs baseline: 2.3361x; 1.0303x over previous
#include <cuda_runtime.h>
#include <cstdint>

// convection_vectors: (N_NODES, 3) float32      -> d_in[0]
// mesh_elements:      (E, 4)       int32        -> d_in[1]
// inv_matrices:       (E, 4, 4)    float32      -> d_in[2]
// out:                (E, 4, 3)    float32      -> d_out
//
// out[e,i,c] = sum_j inv[e,i,j] * conv[mesh[e,j], c]

#define MAX_NODES 400000

// Padded gather table: (N, 4) so each vertex is one aligned 16B load. 6.4 MB -> L2-resident.
__device__ float4 g_conv4[MAX_NODES];

__global__ void __launch_bounds__(128)
pad_conv_kernel(const float* __restrict__ conv, int n)
{
    int i = blockIdx.x * blockDim.x + threadIdx.x;
    if (i >= n) return;
    long b = (long)i * 3;
    g_conv4[i] = make_float4(conv[b], conv[b + 1], conv[b + 2], 0.0f);
}

__device__ __forceinline__ uint32_t smem_u32(const void* p)
{
    uint32_t a;
    asm("{ .reg .u64 t; cvta.to.shared.u64 t, %1; cvt.u32.u64 %0, t; }" : "=r"(a) : "l"(p));
    return a;
}

// One thread per (element,row) unit; each CTA processes TWO consecutive
// 256-row tiles with double-buffered smem + pipelined TMA bulk stores:
//   tile0: compute -> STS buf0 -> sync -> TMA commit buf0   (no wait)
//   tile1: compute -> STS buf1 -> sync -> TMA commit buf1 -> wait_group 0
// Tile1's compute overlaps tile0's TMA drain; CTA count halves.
__global__ void __launch_bounds__(256)
fem_row_tma2_kernel(const int4*   __restrict__ elems,
                    const float4* __restrict__ inv,
                    float*        __restrict__ out,
                    int total_rows)   // 4*E
{
    __shared__ __align__(16) float s_out[2][256 * 3];   // 2 x 3 KB tiles

    const int tile_rows = 256;

#pragma unroll
    for (int it = 0; it < 2; it++) {
        int tile_base = (blockIdx.x * 2 + it) * tile_rows;
        int t = tile_base + threadIdx.x;
        bool full_tile = (tile_base + tile_rows <= total_rows);

        if (t < total_rows) {
            int4 idx = __ldcs(&elems[t >> 2]);
            float4 m = __ldcs(&inv[t]);

            float4 v0 = g_conv4[idx.x];
            float4 v1 = g_conv4[idx.y];
            float4 v2 = g_conv4[idx.z];
            float4 v3 = g_conv4[idx.w];

            float r0 = fmaf(m.x, v0.x, fmaf(m.y, v1.x, fmaf(m.z, v2.x, m.w * v3.x)));
            float r1 = fmaf(m.x, v0.y, fmaf(m.y, v1.y, fmaf(m.z, v2.y, m.w * v3.y)));
            float r2 = fmaf(m.x, v0.z, fmaf(m.y, v1.z, fmaf(m.z, v2.z, m.w * v3.z)));

            if (full_tile) {
                // stride-3 word addresses: gcd(3,32)=1 -> conflict-free
                int w = threadIdx.x * 3;
                s_out[it][w + 0] = r0;
                s_out[it][w + 1] = r1;
                s_out[it][w + 2] = r2;
            } else {
                float* o = out + (long)t * 3;
                __stcs(o + 0, r0);
                __stcs(o + 1, r1);
                __stcs(o + 2, r2);
            }
        }

        if (full_tile) {
            asm volatile("fence.proxy.async.shared::cta;" ::: "memory");
            __syncthreads();
            if (threadIdx.x == 0) {
                uint32_t saddr = smem_u32(s_out[it]);
                float* gptr = out + (long)tile_base * 3;   // 3072B-aligned chunk
                asm volatile(
                    "cp.async.bulk.global.shared::cta.bulk_group [%0], [%1], %2;"
                    :: "l"(gptr), "r"(saddr), "r"(tile_rows * 3 * 4) : "memory");
                asm volatile("cp.async.bulk.commit_group;" ::: "memory");
            }
        }
    }

    // Single drain at CTA end (covers both buffers).
    if (threadIdx.x == 0)
        asm volatile("cp.async.bulk.wait_group 0;" ::: "memory");
}

extern "C" void kernel_launch(void* const* d_in, const int* in_sizes, int n_in,
                              void* d_out, int out_size)
{
    const float* conv  = (const float*)d_in[0];
    const int4*  elems = (const int4*)d_in[1];
    const float4* inv  = (const float4*)d_in[2];
    float* out = (float*)d_out;

    int n_nodes = in_sizes[0] / 3;
    int E = in_sizes[1] / 4;
    int total_rows = 4 * E;

    pad_conv_kernel<<<(n_nodes + 127) / 128, 128>>>(conv, n_nodes);

    int rows_per_cta = 512;   // 2 tiles x 256
    int grid = (total_rows + rows_per_cta - 1) / rows_per_cta;
    fem_row_tma2_kernel<<<grid, 256>>>(elems, inv, out, total_rows);
}